// round 2
// baseline (speedup 1.0000x reference)
#include <cuda_runtime.h>

// ---------------------------------------------------------------------------
// SW-MSA (Swin shifted-window attention), fp32 SIMT baseline.
// B=32, H=W=48, D=384, NH=8, HD=48, WS=6, SS=3 -> 2048 windows x 36 tokens.
// Pipeline: qkv_gemm (gather-fused) -> attn per (win,head) -> proj_gemm.
// ---------------------------------------------------------------------------

namespace {
constexpr int Dm  = 384;
constexpr int TDm = 1152;        // 3*D
constexpr int NHm = 8;
constexpr int HDm = 48;
constexpr int Vm  = 36;          // tokens per window
constexpr int GWm = 2048;        // total windows (32 * 64)
constexpr int Tm  = 73728;       // total tokens
constexpr float SCALE = 0.14433756729740643f;   // 48^-0.5
}

// scratch (static device memory — allocation-free per harness rules)
__device__ float g_qkv[(size_t)3 * GWm * NHm * Vm * HDm];   // [part][win][head][v][hd]
__device__ float g_att[(size_t)Tm * Dm];                    // [b][h][w][d]  (post reverse+roll)

// ---------------------------------------------------------------------------
// Kernel 1: QKV GEMM.  C(73728 x 1152) = gatherA(73728 x 384) @ w_qkv + b_qkv
// Tile 128x64, BK=16, 256 threads, 8x4 microtile.
// A-row m -> token (window-major); gather applies roll(-3,-3) + window partition.
// C scatter writes q/k/v into per-(win,head) contiguous 36x48 tiles.
// ---------------------------------------------------------------------------
__global__ __launch_bounds__(256) void qkv_gemm(const float* __restrict__ x,
                                                const float* __restrict__ wq,
                                                const float* __restrict__ bq)
{
    __shared__ float sA[16][128];
    __shared__ float sB[16][64];
    __shared__ int   soff[128];

    const int t  = threadIdx.x;
    const int m0 = blockIdx.y * 128;
    const int n0 = blockIdx.x * 64;

    if (t < 128) {
        int m  = m0 + t;
        int gw = m / 36, v = m - gw * 36;
        int b  = gw >> 6, wi = gw & 63;
        int wh = wi >> 3, ww = wi & 7;
        int vh = v / 6,  vw = v - vh * 6;
        int sh = wh * 6 + vh + 3; if (sh >= 48) sh -= 48;   // roll(-3)
        int sw = ww * 6 + vw + 3; if (sw >= 48) sw -= 48;
        soff[t] = ((b * 48 + sh) * 48 + sw) * Dm;
    }
    __syncthreads();

    const int ty = t >> 4, tx = t & 15;
    const int arow = t & 127, aseg = (t >> 7) << 3;   // 0 or 8
    const int brow = t >> 4,  bcol = (t & 15) << 2;

    float acc[8][4];
#pragma unroll
    for (int i = 0; i < 8; ++i)
#pragma unroll
        for (int j = 0; j < 4; ++j) acc[i][j] = 0.f;

    const int aoff = soff[arow];

    for (int k0 = 0; k0 < Dm; k0 += 16) {
        float4 a0 = *(const float4*)(x + aoff + k0 + aseg);
        float4 a1 = *(const float4*)(x + aoff + k0 + aseg + 4);
        float4 bv = *(const float4*)(wq + (size_t)(k0 + brow) * TDm + n0 + bcol);
        sA[aseg + 0][arow] = a0.x;  sA[aseg + 1][arow] = a0.y;
        sA[aseg + 2][arow] = a0.z;  sA[aseg + 3][arow] = a0.w;
        sA[aseg + 4][arow] = a1.x;  sA[aseg + 5][arow] = a1.y;
        sA[aseg + 6][arow] = a1.z;  sA[aseg + 7][arow] = a1.w;
        *(float4*)&sB[brow][bcol] = bv;
        __syncthreads();
#pragma unroll
        for (int kk = 0; kk < 16; ++kk) {
            const float4* pa = (const float4*)&sA[kk][ty << 3];
            float4 av0 = pa[0], av1 = pa[1];
            float4 bvv = *(const float4*)&sB[kk][tx << 2];
            float a[8] = {av0.x, av0.y, av0.z, av0.w, av1.x, av1.y, av1.z, av1.w};
            float bb[4] = {bvv.x, bvv.y, bvv.z, bvv.w};
#pragma unroll
            for (int i = 0; i < 8; ++i)
#pragma unroll
                for (int j = 0; j < 4; ++j)
                    acc[i][j] += a[i] * bb[j];
        }
        __syncthreads();
    }

    // epilogue: scatter into g_qkv[part][win][head][v][hd] (+bias)
    const int n    = n0 + (tx << 2);
    const int part = n / 384;
    const int r    = n - part * 384;
    const int head = r / 48;
    const int hd   = r - head * 48;           // 4-group never crosses a head boundary
    const float b0 = bq[n], b1 = bq[n + 1], b2 = bq[n + 2], b3 = bq[n + 3];
    const size_t pbase = (size_t)part * GWm * (NHm * Vm * HDm)
                       + (size_t)head * (Vm * HDm) + hd;
#pragma unroll
    for (int i = 0; i < 8; ++i) {
        int m  = m0 + (ty << 3) + i;
        int gw = m / 36, v = m - gw * 36;
        size_t o = pbase + (size_t)gw * (NHm * Vm * HDm) + v * HDm;
        g_qkv[o + 0] = acc[i][0] + b0;
        g_qkv[o + 1] = acc[i][1] + b1;
        g_qkv[o + 2] = acc[i][2] + b2;
        g_qkv[o + 3] = acc[i][3] + b3;
    }
}

// ---------------------------------------------------------------------------
// Kernel 2: attention per (window, head). 2048*8 = 16384 blocks, 256 threads.
// S = softmax(q k^T * scale + mask), O = S v. Store fused with reverse+roll(+3).
// ---------------------------------------------------------------------------
__global__ __launch_bounds__(256) void attn_kernel()
{
    __shared__ float qs[36][49];
    __shared__ float ks[36][49];
    __shared__ float vs[36][49];
    __shared__ float sc[36][37];
    __shared__ int   rid[36];

    const int t    = threadIdx.x;
    const int gw   = blockIdx.x >> 3;
    const int head = blockIdx.x & 7;

    const size_t PART = (size_t)GWm * NHm * Vm * HDm;
    const float* gq = g_qkv + (size_t)gw * (NHm * Vm * HDm) + (size_t)head * (Vm * HDm);
    const float* gk = gq + PART;
    const float* gv = gq + 2 * PART;

    for (int idx = t; idx < Vm * HDm; idx += 256) {
        int i = idx / 48, d = idx - i * 48;
        qs[i][d] = gq[idx];
        ks[i][d] = gk[idx];
        vs[i][d] = gv[idx];
    }
    const int wi = gw & 63;
    const int wh = wi >> 3, ww = wi & 7;
    if (t < 36) {
        int vh = t / 6, vw = t - vh * 6;
        int y = wh * 6 + vh + 3; if (y >= 48) y -= 48;
        int xq = ww * 6 + vw + 3; if (xq >= 48) xq -= 48;
        rid[t] = ((y >= 3) ? 2 : 0) + ((xq >= 3) ? 1 : 0);
    }
    __syncthreads();

    // scores: thread -> (row i, 6-wide j group); q value reused across 6 cols
    if (t < 216) {
        int i = t / 6, j0 = (t - i * 6) * 6;
        float acc[6] = {0.f, 0.f, 0.f, 0.f, 0.f, 0.f};
#pragma unroll 4
        for (int kx = 0; kx < 48; ++kx) {
            float qv = qs[i][kx];
#pragma unroll
            for (int jj = 0; jj < 6; ++jj)
                acc[jj] += qv * ks[j0 + jj][kx];
        }
        int ri = rid[i];
#pragma unroll
        for (int jj = 0; jj < 6; ++jj) {
            float val = acc[jj] * SCALE;
            if (rid[j0 + jj] != ri) val = -1e30f;
            sc[i][j0 + jj] = val;
        }
    }
    __syncthreads();

    // softmax: one thread per row (36 rows; cheap vs GEMM phases)
    if (t < 36) {
        float mx = -3.4e38f;
        for (int j = 0; j < 36; ++j) mx = fmaxf(mx, sc[t][j]);
        float sum = 0.f;
        for (int j = 0; j < 36; ++j) {
            float e = __expf(sc[t][j] - mx);
            sc[t][j] = e;
            sum += e;
        }
        float inv = 1.f / sum;
        for (int j = 0; j < 36; ++j) sc[t][j] *= inv;
    }
    __syncthreads();

    // O = S @ V: thread -> (row i, 8-wide d group); S value broadcast across 8
    if (t < 216) {
        int i = t / 6, d0 = (t - i * 6) * 8;
        float acc[8] = {0.f, 0.f, 0.f, 0.f, 0.f, 0.f, 0.f, 0.f};
#pragma unroll 4
        for (int j = 0; j < 36; ++j) {
            float sv = sc[i][j];
#pragma unroll
            for (int dd = 0; dd < 8; ++dd)
                acc[dd] += sv * vs[j][d0 + dd];
        }
        int b  = gw >> 6;
        int vh = i / 6, vw = i - vh * 6;
        int dh = wh * 6 + vh + 3; if (dh >= 48) dh -= 48;   // reverse + roll(+3)
        int dw = ww * 6 + vw + 3; if (dw >= 48) dw -= 48;
        size_t o = ((size_t)(b * 48 + dh) * 48 + dw) * Dm + head * HDm + d0;
#pragma unroll
        for (int dd = 0; dd < 8; ++dd) g_att[o + dd] = acc[dd];
    }
}

// ---------------------------------------------------------------------------
// Kernel 3: proj GEMM.  out(73728 x 384) = g_att @ w_proj + b_proj
// ---------------------------------------------------------------------------
__global__ __launch_bounds__(256) void proj_gemm(const float* __restrict__ wp,
                                                 const float* __restrict__ bp,
                                                 float* __restrict__ out)
{
    __shared__ float sA[16][128];
    __shared__ float sB[16][64];

    const int t  = threadIdx.x;
    const int m0 = blockIdx.y * 128;
    const int n0 = blockIdx.x * 64;

    const int ty = t >> 4, tx = t & 15;
    const int arow = t & 127, aseg = (t >> 7) << 3;
    const int brow = t >> 4,  bcol = (t & 15) << 2;

    float acc[8][4];
#pragma unroll
    for (int i = 0; i < 8; ++i)
#pragma unroll
        for (int j = 0; j < 4; ++j) acc[i][j] = 0.f;

    const float* A = g_att + (size_t)(m0 + arow) * Dm;

    for (int k0 = 0; k0 < Dm; k0 += 16) {
        float4 a0 = *(const float4*)(A + k0 + aseg);
        float4 a1 = *(const float4*)(A + k0 + aseg + 4);
        float4 bv = *(const float4*)(wp + (size_t)(k0 + brow) * Dm + n0 + bcol);
        sA[aseg + 0][arow] = a0.x;  sA[aseg + 1][arow] = a0.y;
        sA[aseg + 2][arow] = a0.z;  sA[aseg + 3][arow] = a0.w;
        sA[aseg + 4][arow] = a1.x;  sA[aseg + 5][arow] = a1.y;
        sA[aseg + 6][arow] = a1.z;  sA[aseg + 7][arow] = a1.w;
        *(float4*)&sB[brow][bcol] = bv;
        __syncthreads();
#pragma unroll
        for (int kk = 0; kk < 16; ++kk) {
            const float4* pa = (const float4*)&sA[kk][ty << 3];
            float4 av0 = pa[0], av1 = pa[1];
            float4 bvv = *(const float4*)&sB[kk][tx << 2];
            float a[8] = {av0.x, av0.y, av0.z, av0.w, av1.x, av1.y, av1.z, av1.w};
            float bb[4] = {bvv.x, bvv.y, bvv.z, bvv.w};
#pragma unroll
            for (int i = 0; i < 8; ++i)
#pragma unroll
                for (int j = 0; j < 4; ++j)
                    acc[i][j] += a[i] * bb[j];
        }
        __syncthreads();
    }

    const int n = n0 + (tx << 2);
    const float b0 = bp[n], b1 = bp[n + 1], b2 = bp[n + 2], b3 = bp[n + 3];
#pragma unroll
    for (int i = 0; i < 8; ++i) {
        size_t o = (size_t)(m0 + (ty << 3) + i) * Dm + n;
        out[o + 0] = acc[i][0] + b0;
        out[o + 1] = acc[i][1] + b1;
        out[o + 2] = acc[i][2] + b2;
        out[o + 3] = acc[i][3] + b3;
    }
}

// ---------------------------------------------------------------------------
extern "C" void kernel_launch(void* const* d_in, const int* in_sizes, int n_in,
                              void* d_out, int out_size)
{
    const float* x     = (const float*)d_in[0];
    const float* wqkv  = (const float*)d_in[1];
    const float* bqkv  = (const float*)d_in[2];
    const float* wproj = (const float*)d_in[3];
    const float* bproj = (const float*)d_in[4];
    float* out = (float*)d_out;

    // M=73728 -> 576 row-blocks of 128; N=1152 -> 18 col-blocks of 64
    qkv_gemm<<<dim3(18, 576), 256>>>(x, wqkv, bqkv);
    attn_kernel<<<GWm * NHm, 256>>>();
    proj_gemm<<<dim3(6, 576), 256>>>(wproj, bproj, out);
}

// round 9
// speedup vs baseline: 1.3571x; 1.3571x over previous
#include <cuda_runtime.h>
#include <cstdint>
#include <mma.h>

using namespace nvcuda;

// ---------------------------------------------------------------------------
// SW-MSA on GB300 (compute_103-portable).
// GEMMs: wmma m16n16k8 tf32 (compiler-owned fragment layouts — no hand packing).
// Attention: fp32 SIMT per (window, head), proven correct in Round 2.
// B=32, H=W=48, D=384, NH=8, HD=48, WS=6, SS=3.
// ---------------------------------------------------------------------------

namespace {
constexpr int Dm  = 384;
constexpr int TDm = 1152;
constexpr int NHm = 8;
constexpr int HDm = 48;
constexpr int Vm  = 36;
constexpr int GWm = 2048;
constexpr int Tm  = 73728;
constexpr float ATT_SCALE = 0.14433756729740643f;   // 48^-0.5

constexpr int NCH  = 12;        // K chunks of 32 (K = 384)
constexpr int ALD  = 40;        // A stage ld (floats): 128 x 40, pad vs bank conflicts
constexpr int BLD  = 136;       // B stage ld: 32 x 136
constexpr int CLD  = 132;       // C smem tile ld: 128 x 132
constexpr int AST  = 128 * ALD;             // 5120 floats
constexpr int BST  = 32 * BLD;              // 4352 floats
constexpr int STG  = AST + BST;             // 9472 floats per stage
constexpr int SMEM_BYTES = 2 * STG * 4;     // 75776 B (C tile 67584 B reuses it)
constexpr size_t PARTsz = (size_t)GWm * NHm * Vm * HDm;
}

// static device scratch (allocation-free per harness rules)
__device__ float g_qkv[3 * PARTsz];                 // [part][win][head][v][hd]
__device__ float g_att[(size_t)Tm * Dm];            // attn out, row-major [token][D]

// ---------------- helpers ----------------
__device__ __forceinline__ uint32_t smem_u32(const void* p) {
    uint32_t a;
    asm("{ .reg .u64 t; cvta.to.shared.u64 t, %1; cvt.u32.u64 %0, t; }"
        : "=r"(a) : "l"(p));
    return a;
}
__device__ __forceinline__ void cpa16(uint32_t dst, const void* src) {
    asm volatile("cp.async.cg.shared.global [%0], [%1], 16;" :: "r"(dst), "l"(src));
}
__device__ __forceinline__ size_t gather_off(int m) {   // roll(-3,-3) + win partition
    int gw = m / 36, v = m - gw * 36;
    int b  = gw >> 6, wi = gw & 63;
    int wh = wi >> 3, ww = wi & 7;
    int vh = v / 6,  vw = v - vh * 6;
    int sh = wh * 6 + vh + 3; if (sh >= 48) sh -= 48;
    int sw = ww * 6 + vw + 3; if (sw >= 48) sw -= 48;
    return (size_t)((b * 48 + sh) * 48 + sw) * Dm;
}

// ---------------------------------------------------------------------------
// wmma tf32 GEMM. CTA tile 128x128, 8 warps in 2(m) x 4(n), warp tile 64x32.
// K streamed in 32-chunks, double-buffered cp.async.
// MODE 0: A = x with roll/window gather, W = w_qkv -> scatter into g_qkv.
// MODE 1: A = g_att (row-major),       W = w_proj -> row-major into outp.
// ---------------------------------------------------------------------------
template<int MODE>
__global__ __launch_bounds__(256) void gemm_wmma(const float* __restrict__ Ain,
                                                 const float* __restrict__ W,
                                                 const float* __restrict__ bias,
                                                 float* __restrict__ outp, int N)
{
    extern __shared__ float sm[];
    const int t = threadIdx.x, wid = t >> 5;
    const int wm = wid >> 2, wn = wid & 3;        // 2 x 4 warp grid
    const int mt = blockIdx.y, nt = blockIdx.x;

    const float* Abase = (MODE == 0) ? Ain : g_att;

    // ---- staging assignments (fixed per thread) ----
    const int ar = t >> 1, ah = (t & 1) * 16;     // A: 2 threads/row, 16 floats each
    size_t aoff = (MODE == 0) ? gather_off(mt * 128 + ar)
                              : (size_t)(mt * 128 + ar) * Dm;
    const float* asrc = Abase + aoff + ah;
    const int bk = t >> 3, bs = (t & 7) * 16;     // B: 8 threads/row, 16 floats each
    const float* bsrc = W + (size_t)bk * N + nt * 128 + bs;

    auto stage_cp = [&](int c, int s) {
        float* dst = sm + s * STG;
        uint32_t sa = smem_u32(dst + ar * ALD + ah);
        uint32_t sb = smem_u32(dst + AST + bk * BLD + bs);
        const float* ap = asrc + c * 32;
        const float* bp = bsrc + (size_t)c * 32 * N;
#pragma unroll
        for (int j = 0; j < 4; ++j) {
            cpa16(sa + j * 16u, ap + j * 4);
            cpa16(sb + j * 16u, bp + j * 4);
        }
        asm volatile("cp.async.commit_group;");
    };

    wmma::fragment<wmma::accumulator, 16, 16, 8, float> acc[4][2];
#pragma unroll
    for (int mi = 0; mi < 4; ++mi)
#pragma unroll
        for (int nj = 0; nj < 2; ++nj)
            wmma::fill_fragment(acc[mi][nj], 0.0f);

    stage_cp(0, 0);

    for (int c = 0; c < NCH; ++c) {
        if (c + 1 < NCH) {
            stage_cp(c + 1, (c + 1) & 1);
            asm volatile("cp.async.wait_group 1;" ::: "memory");
        } else {
            asm volatile("cp.async.wait_group 0;" ::: "memory");
        }
        __syncthreads();

        const float* As = sm + (c & 1) * STG;
        const float* Bs = As + AST;
#pragma unroll
        for (int ks = 0; ks < 4; ++ks) {
            wmma::fragment<wmma::matrix_a, 16, 16, 8, wmma::precision::tf32,
                           wmma::row_major> af[4];
            wmma::fragment<wmma::matrix_b, 16, 16, 8, wmma::precision::tf32,
                           wmma::row_major> bf[2];
#pragma unroll
            for (int mi = 0; mi < 4; ++mi) {
                wmma::load_matrix_sync(af[mi],
                    As + (wm * 64 + mi * 16) * ALD + ks * 8, ALD);
#pragma unroll
                for (int e = 0; e < af[mi].num_elements; ++e)
                    af[mi].x[e] = wmma::__float_to_tf32(af[mi].x[e]);
            }
#pragma unroll
            for (int nj = 0; nj < 2; ++nj) {
                wmma::load_matrix_sync(bf[nj],
                    Bs + (ks * 8) * BLD + wn * 32 + nj * 16, BLD);
#pragma unroll
                for (int e = 0; e < bf[nj].num_elements; ++e)
                    bf[nj].x[e] = wmma::__float_to_tf32(bf[nj].x[e]);
            }
#pragma unroll
            for (int mi = 0; mi < 4; ++mi)
#pragma unroll
                for (int nj = 0; nj < 2; ++nj)
                    wmma::mma_sync(acc[mi][nj], af[mi], bf[nj], acc[mi][nj]);
        }
        __syncthreads();
    }

    // ---- epilogue: compiler-owned C store to SMEM, then generic scatter ----
    float* Cs = sm;   // stages no longer needed
#pragma unroll
    for (int mi = 0; mi < 4; ++mi)
#pragma unroll
        for (int nj = 0; nj < 2; ++nj)
            wmma::store_matrix_sync(Cs + (wm * 64 + mi * 16) * CLD + wn * 32 + nj * 16,
                                    acc[mi][nj], CLD, wmma::mem_row_major);
    __syncthreads();

    for (int f = t; f < 128 * 32; f += 256) {        // 128 rows x 32 float4-cols
        int r  = f >> 5;
        int c4 = (f & 31) * 4;
        float4 v = *reinterpret_cast<const float4*>(Cs + r * CLD + c4);
        int n = nt * 128 + c4;
        v.x += bias[n];  v.y += bias[n + 1];  v.z += bias[n + 2];  v.w += bias[n + 3];
        int m = mt * 128 + r;
        if (MODE == 1) {
            *reinterpret_cast<float4*>(outp + (size_t)m * Dm + n) = v;
        } else {
            int gw = m / 36, vv = m - gw * 36;
            int part = n / 384;
            int pr   = n - part * 384;
            int head = pr / 48, hd = pr - head * 48;   // c4 mult of 4 -> hd <= 44
            *reinterpret_cast<float4*>(g_qkv + (size_t)part * PARTsz
                                       + (size_t)gw * (NHm * Vm * HDm)
                                       + (size_t)head * (Vm * HDm)
                                       + (size_t)vv * HDm + hd) = v;
        }
    }
}

// ---------------------------------------------------------------------------
// Attention per (window, head) — proven correct in Round 2.
// ---------------------------------------------------------------------------
__global__ __launch_bounds__(256) void attn_kernel()
{
    __shared__ float qs[36][49];
    __shared__ float ks[36][49];
    __shared__ float vs[36][49];
    __shared__ float sc[36][37];
    __shared__ int   rid[36];

    const int t    = threadIdx.x;
    const int gw   = blockIdx.x >> 3;
    const int head = blockIdx.x & 7;

    const float* gq = g_qkv + (size_t)gw * (NHm * Vm * HDm) + (size_t)head * (Vm * HDm);
    const float* gk = gq + PARTsz;
    const float* gv = gq + 2 * PARTsz;

    for (int idx = t; idx < Vm * HDm; idx += 256) {
        int i = idx / 48, d = idx - i * 48;
        qs[i][d] = gq[idx];
        ks[i][d] = gk[idx];
        vs[i][d] = gv[idx];
    }
    const int wi = gw & 63;
    const int wh = wi >> 3, ww = wi & 7;
    if (t < 36) {
        int vh = t / 6, vw = t - vh * 6;
        int y  = wh * 6 + vh + 3; if (y  >= 48) y  -= 48;
        int xq = ww * 6 + vw + 3; if (xq >= 48) xq -= 48;
        rid[t] = ((y >= 3) ? 2 : 0) + ((xq >= 3) ? 1 : 0);
    }
    __syncthreads();

    if (t < 216) {
        int i = t / 6, j0 = (t - i * 6) * 6;
        float acc[6] = {0.f, 0.f, 0.f, 0.f, 0.f, 0.f};
#pragma unroll 4
        for (int kx = 0; kx < 48; ++kx) {
            float qv = qs[i][kx];
#pragma unroll
            for (int jj = 0; jj < 6; ++jj)
                acc[jj] += qv * ks[j0 + jj][kx];
        }
        int ri = rid[i];
#pragma unroll
        for (int jj = 0; jj < 6; ++jj) {
            float val = acc[jj] * ATT_SCALE;
            if (rid[j0 + jj] != ri) val = -1e30f;
            sc[i][j0 + jj] = val;
        }
    }
    __syncthreads();

    if (t < 36) {
        float mx = -3.4e38f;
        for (int j = 0; j < 36; ++j) mx = fmaxf(mx, sc[t][j]);
        float sum = 0.f;
        for (int j = 0; j < 36; ++j) {
            float e = __expf(sc[t][j] - mx);
            sc[t][j] = e;
            sum += e;
        }
        float inv = 1.f / sum;
        for (int j = 0; j < 36; ++j) sc[t][j] *= inv;
    }
    __syncthreads();

    if (t < 216) {
        int i = t / 6, d0 = (t - i * 6) * 8;
        float acc[8] = {0.f, 0.f, 0.f, 0.f, 0.f, 0.f, 0.f, 0.f};
#pragma unroll 4
        for (int j = 0; j < 36; ++j) {
            float sv = sc[i][j];
#pragma unroll
            for (int dd = 0; dd < 8; ++dd)
                acc[dd] += sv * vs[j][d0 + dd];
        }
        int b  = gw >> 6;
        int vh = i / 6, vw = i - vh * 6;
        int dh = wh * 6 + vh + 3; if (dh >= 48) dh -= 48;   // reverse + roll(+3)
        int dw = ww * 6 + vw + 3; if (dw >= 48) dw -= 48;
        size_t o = ((size_t)(b * 48 + dh) * 48 + dw) * Dm + head * HDm + d0;
#pragma unroll
        for (int dd = 0; dd < 8; ++dd) g_att[o + dd] = acc[dd];
    }
}

// ---------------------------------------------------------------------------
extern "C" void kernel_launch(void* const* d_in, const int* in_sizes, int n_in,
                              void* d_out, int out_size)
{
    const float* x     = (const float*)d_in[0];
    const float* wqkv  = (const float*)d_in[1];
    const float* bqkv  = (const float*)d_in[2];
    const float* wproj = (const float*)d_in[3];
    const float* bproj = (const float*)d_in[4];
    float* out = (float*)d_out;

    cudaFuncSetAttribute(gemm_wmma<0>, cudaFuncAttributeMaxDynamicSharedMemorySize, SMEM_BYTES);
    cudaFuncSetAttribute(gemm_wmma<1>, cudaFuncAttributeMaxDynamicSharedMemorySize, SMEM_BYTES);

    // qkv: M=73728 (576 tiles), N=1152 (9 tiles)
    gemm_wmma<0><<<dim3(9, 576), 256, SMEM_BYTES>>>(x, wqkv, bqkv, nullptr, TDm);
    attn_kernel<<<GWm * NHm, 256>>>();
    // proj: N=384 (3 tiles); A = g_att referenced in-kernel
    gemm_wmma<1><<<dim3(3, 576), 256, SMEM_BYTES>>>(nullptr, wproj, bproj, out, Dm);
}

// round 10
// speedup vs baseline: 1.4955x; 1.1020x over previous
#include <cuda_runtime.h>
#include <cstdint>
#include <mma.h>

using namespace nvcuda;

// ---------------------------------------------------------------------------
// SW-MSA on GB300 (compute_103-portable).
// GEMMs: wmma m16n16k8 tf32, 3-stage cp.async pipeline, 2 CTAs/SM.
// Attention: fp32 SIMT per (window, head), register-resident softmax.
// ---------------------------------------------------------------------------

namespace {
constexpr int Dm  = 384;
constexpr int TDm = 1152;
constexpr int NHm = 8;
constexpr int HDm = 48;
constexpr int Vm  = 36;
constexpr int GWm = 2048;
constexpr int Tm  = 73728;
constexpr float ATT_SCALE = 0.14433756729740643f;   // 48^-0.5

constexpr int NCH  = 12;        // K chunks of 32 (K = 384)
constexpr int ALD  = 36;        // A stage ld: 128 x 36 (4-bank row stride)
constexpr int BLD  = 132;       // B stage ld: 32 x 132
constexpr int CLD  = 132;       // C smem tile ld: 128 x 132
constexpr int AST  = 128 * ALD;             // 4608 floats
constexpr int BST  = 32 * BLD;              // 4224 floats
constexpr int STG  = AST + BST;             // 8832 floats per stage
constexpr int NSTG = 3;
constexpr int SMEM_BYTES = NSTG * STG * 4;  // 105984 B (C tile 67584 B reuses it)
constexpr size_t PARTsz = (size_t)GWm * NHm * Vm * HDm;
}

// static device scratch (allocation-free per harness rules)
__device__ float g_qkv[3 * PARTsz];                 // [part][win][head][v][hd]
__device__ float g_att[(size_t)Tm * Dm];            // attn out, row-major [token][D]

// ---------------- helpers ----------------
__device__ __forceinline__ uint32_t smem_u32(const void* p) {
    uint32_t a;
    asm("{ .reg .u64 t; cvta.to.shared.u64 t, %1; cvt.u32.u64 %0, t; }"
        : "=r"(a) : "l"(p));
    return a;
}
__device__ __forceinline__ void cpa16(uint32_t dst, const void* src) {
    asm volatile("cp.async.cg.shared.global [%0], [%1], 16;" :: "r"(dst), "l"(src));
}
__device__ __forceinline__ size_t gather_off(int m) {   // roll(-3,-3) + win partition
    int gw = m / 36, v = m - gw * 36;
    int b  = gw >> 6, wi = gw & 63;
    int wh = wi >> 3, ww = wi & 7;
    int vh = v / 6,  vw = v - vh * 6;
    int sh = wh * 6 + vh + 3; if (sh >= 48) sh -= 48;
    int sw = ww * 6 + vw + 3; if (sw >= 48) sw -= 48;
    return (size_t)((b * 48 + sh) * 48 + sw) * Dm;
}

// ---------------------------------------------------------------------------
// wmma tf32 GEMM. CTA tile 128x128, 8 warps in 2(m) x 4(n), warp tile 64x32.
// 3-stage cp.async pipeline; __launch_bounds__(256,2) -> 2 CTAs/SM.
// MODE 0: A = x with roll/window gather, W = w_qkv -> scatter into g_qkv.
// MODE 1: A = g_att (row-major),        W = w_proj -> row-major into outp.
// ---------------------------------------------------------------------------
template<int MODE>
__global__ __launch_bounds__(256, 2) void gemm_wmma(const float* __restrict__ Ain,
                                                    const float* __restrict__ W,
                                                    const float* __restrict__ bias,
                                                    float* __restrict__ outp, int N)
{
    extern __shared__ float sm[];
    const int t = threadIdx.x, wid = t >> 5;
    const int wm = wid >> 2, wn = wid & 3;        // 2 x 4 warp grid
    const int mt = blockIdx.y, nt = blockIdx.x;

    const float* Abase = (MODE == 0) ? Ain : g_att;

    // ---- staging assignments (fixed per thread) ----
    const int ar = t >> 1, ah = (t & 1) * 16;     // A: 2 threads/row, 16 floats each
    size_t aoff = (MODE == 0) ? gather_off(mt * 128 + ar)
                              : (size_t)(mt * 128 + ar) * Dm;
    const float* asrc = Abase + aoff + ah;
    const int bk = t >> 3, bs = (t & 7) * 16;     // B: 8 threads/row, 16 floats each
    const float* bsrc = W + (size_t)bk * N + nt * 128 + bs;

    const uint32_t sa0 = smem_u32(sm + ar * ALD + ah);
    const uint32_t sb0 = smem_u32(sm + AST + bk * BLD + bs);

    auto stage_cp = [&](int c, int s) {
        uint32_t sa = sa0 + (uint32_t)s * (STG * 4);
        uint32_t sb = sb0 + (uint32_t)s * (STG * 4);
        const float* ap = asrc + c * 32;
        const float* bp = bsrc + (size_t)c * 32 * N;
#pragma unroll
        for (int j = 0; j < 4; ++j) {
            cpa16(sa + j * 16u, ap + j * 4);
            cpa16(sb + j * 16u, bp + j * 4);
        }
        asm volatile("cp.async.commit_group;");
    };

    wmma::fragment<wmma::accumulator, 16, 16, 8, float> acc[4][2];
#pragma unroll
    for (int mi = 0; mi < 4; ++mi)
#pragma unroll
        for (int nj = 0; nj < 2; ++nj)
            wmma::fill_fragment(acc[mi][nj], 0.0f);

    stage_cp(0, 0);
    stage_cp(1, 1);

    int s_cur = 0, s_pf = 2;   // rolling stage indices (mod 3)
    for (int c = 0; c < NCH; ++c) {
        if (c + 2 < NCH) {
            stage_cp(c + 2, s_pf);
            if (++s_pf == NSTG) s_pf = 0;
            asm volatile("cp.async.wait_group 2;" ::: "memory");
        } else if (c + 1 < NCH) {
            asm volatile("cp.async.wait_group 1;" ::: "memory");
        } else {
            asm volatile("cp.async.wait_group 0;" ::: "memory");
        }
        __syncthreads();

        const float* As = sm + s_cur * STG;
        const float* Bs = As + AST;
        if (++s_cur == NSTG) s_cur = 0;
#pragma unroll
        for (int ks = 0; ks < 4; ++ks) {
            wmma::fragment<wmma::matrix_a, 16, 16, 8, wmma::precision::tf32,
                           wmma::row_major> af[4];
            wmma::fragment<wmma::matrix_b, 16, 16, 8, wmma::precision::tf32,
                           wmma::row_major> bf[2];
#pragma unroll
            for (int mi = 0; mi < 4; ++mi) {
                wmma::load_matrix_sync(af[mi],
                    As + (wm * 64 + mi * 16) * ALD + ks * 8, ALD);
#pragma unroll
                for (int e = 0; e < af[mi].num_elements; ++e)
                    af[mi].x[e] = wmma::__float_to_tf32(af[mi].x[e]);
            }
#pragma unroll
            for (int nj = 0; nj < 2; ++nj) {
                wmma::load_matrix_sync(bf[nj],
                    Bs + (ks * 8) * BLD + wn * 32 + nj * 16, BLD);
#pragma unroll
                for (int e = 0; e < bf[nj].num_elements; ++e)
                    bf[nj].x[e] = wmma::__float_to_tf32(bf[nj].x[e]);
            }
#pragma unroll
            for (int mi = 0; mi < 4; ++mi)
#pragma unroll
                for (int nj = 0; nj < 2; ++nj)
                    wmma::mma_sync(acc[mi][nj], af[mi], bf[nj], acc[mi][nj]);
        }
        __syncthreads();
    }

    // ---- epilogue: compiler-owned C store to SMEM, then generic scatter ----
    float* Cs = sm;   // stages no longer needed
#pragma unroll
    for (int mi = 0; mi < 4; ++mi)
#pragma unroll
        for (int nj = 0; nj < 2; ++nj)
            wmma::store_matrix_sync(Cs + (wm * 64 + mi * 16) * CLD + wn * 32 + nj * 16,
                                    acc[mi][nj], CLD, wmma::mem_row_major);
    __syncthreads();

    for (int f = t; f < 128 * 32; f += 256) {        // 128 rows x 32 float4-cols
        int r  = f >> 5;
        int c4 = (f & 31) * 4;
        float4 v = *reinterpret_cast<const float4*>(Cs + r * CLD + c4);
        int n = nt * 128 + c4;
        v.x += bias[n];  v.y += bias[n + 1];  v.z += bias[n + 2];  v.w += bias[n + 3];
        int m = mt * 128 + r;
        if (MODE == 1) {
            *reinterpret_cast<float4*>(outp + (size_t)m * Dm + n) = v;
        } else {
            int gw = m / 36, vv = m - gw * 36;
            int part = n / 384;
            int pr   = n - part * 384;
            int head = pr / 48, hd = pr - head * 48;
            *reinterpret_cast<float4*>(g_qkv + (size_t)part * PARTsz
                                       + (size_t)gw * (NHm * Vm * HDm)
                                       + (size_t)head * (Vm * HDm)
                                       + (size_t)vv * HDm + hd) = v;
        }
    }
}

// ---------------------------------------------------------------------------
// Attention per (window, head). Scores held in registers through softmax;
// row max/sum via 216-thread partials + 36-thread 6-way reductions.
// ---------------------------------------------------------------------------
__global__ __launch_bounds__(256) void attn_kernel()
{
    __shared__ float qs[36][49];
    __shared__ float ks[36][49];
    __shared__ float vs[36][49];
    __shared__ float sc[36][37];
    __shared__ float pmx[36][6];
    __shared__ float psum[36][6];
    __shared__ float rmax[36];
    __shared__ float rinv[36];
    __shared__ int   rid[36];

    const int t    = threadIdx.x;
    const int gw   = blockIdx.x >> 3;
    const int head = blockIdx.x & 7;

    const float* gq = g_qkv + (size_t)gw * (NHm * Vm * HDm) + (size_t)head * (Vm * HDm);
    const float* gk = gq + PARTsz;
    const float* gv = gq + 2 * PARTsz;

    for (int idx = t; idx < Vm * HDm; idx += 256) {
        int i = idx / 48, d = idx - i * 48;
        qs[i][d] = gq[idx];
        ks[i][d] = gk[idx];
        vs[i][d] = gv[idx];
    }
    const int wi = gw & 63;
    const int wh = wi >> 3, ww = wi & 7;
    if (t < 36) {
        int vh = t / 6, vw = t - vh * 6;
        int y  = wh * 6 + vh + 3; if (y  >= 48) y  -= 48;
        int xq = ww * 6 + vw + 3; if (xq >= 48) xq -= 48;
        rid[t] = ((y >= 3) ? 2 : 0) + ((xq >= 3) ? 1 : 0);
    }
    __syncthreads();

    const int i  = t / 6;            // row (valid when t < 216)
    const int jg = t - i * 6;        // 6-col group
    const int j0 = jg * 6;
    float acc[6];

    if (t < 216) {
#pragma unroll
        for (int jj = 0; jj < 6; ++jj) acc[jj] = 0.f;
#pragma unroll 4
        for (int kx = 0; kx < 48; ++kx) {
            float qv = qs[i][kx];
#pragma unroll
            for (int jj = 0; jj < 6; ++jj)
                acc[jj] += qv * ks[j0 + jj][kx];
        }
        int ri = rid[i];
        float m6 = -3.4e38f;
#pragma unroll
        for (int jj = 0; jj < 6; ++jj) {
            float val = acc[jj] * ATT_SCALE;
            if (rid[j0 + jj] != ri) val = -1e30f;
            acc[jj] = val;
            m6 = fmaxf(m6, val);
        }
        pmx[i][jg] = m6;
    }
    __syncthreads();

    if (t < 36) {
        float m = pmx[t][0];
#pragma unroll
        for (int g = 1; g < 6; ++g) m = fmaxf(m, pmx[t][g]);
        rmax[t] = m;
    }
    __syncthreads();

    if (t < 216) {
        float m = rmax[i], s = 0.f;
#pragma unroll
        for (int jj = 0; jj < 6; ++jj) {
            acc[jj] = __expf(acc[jj] - m);
            s += acc[jj];
        }
        psum[i][jg] = s;
    }
    __syncthreads();

    if (t < 36) {
        float s = psum[t][0];
#pragma unroll
        for (int g = 1; g < 6; ++g) s += psum[t][g];
        rinv[t] = 1.f / s;
    }
    __syncthreads();

    if (t < 216) {
        float inv = rinv[i];
#pragma unroll
        for (int jj = 0; jj < 6; ++jj) sc[i][j0 + jj] = acc[jj] * inv;
    }
    __syncthreads();

    if (t < 216) {
        const int d0 = jg * 8;
        float av[8] = {0.f, 0.f, 0.f, 0.f, 0.f, 0.f, 0.f, 0.f};
#pragma unroll 4
        for (int j = 0; j < 36; ++j) {
            float sv = sc[i][j];
#pragma unroll
            for (int dd = 0; dd < 8; ++dd)
                av[dd] += sv * vs[j][d0 + dd];
        }
        int b  = gw >> 6;
        int vh = i / 6, vw = i - vh * 6;
        int dh = wh * 6 + vh + 3; if (dh >= 48) dh -= 48;   // reverse + roll(+3)
        int dw = ww * 6 + vw + 3; if (dw >= 48) dw -= 48;
        size_t o = ((size_t)(b * 48 + dh) * 48 + dw) * Dm + head * HDm + d0;
#pragma unroll
        for (int dd = 0; dd < 8; ++dd) g_att[o + dd] = av[dd];
    }
}

// ---------------------------------------------------------------------------
extern "C" void kernel_launch(void* const* d_in, const int* in_sizes, int n_in,
                              void* d_out, int out_size)
{
    const float* x     = (const float*)d_in[0];
    const float* wqkv  = (const float*)d_in[1];
    const float* bqkv  = (const float*)d_in[2];
    const float* wproj = (const float*)d_in[3];
    const float* bproj = (const float*)d_in[4];
    float* out = (float*)d_out;

    cudaFuncSetAttribute(gemm_wmma<0>, cudaFuncAttributeMaxDynamicSharedMemorySize, SMEM_BYTES);
    cudaFuncSetAttribute(gemm_wmma<1>, cudaFuncAttributeMaxDynamicSharedMemorySize, SMEM_BYTES);

    gemm_wmma<0><<<dim3(9, 576), 256, SMEM_BYTES>>>(x, wqkv, bqkv, nullptr, TDm);
    attn_kernel<<<GWm * NHm, 256>>>();
    gemm_wmma<1><<<dim3(3, 576), 256, SMEM_BYTES>>>(nullptr, wproj, bproj, out, Dm);
}